// round 14
// baseline (speedup 1.0000x reference)
#include <cuda_runtime.h>
#include <cuda_fp16.h>
#include <math.h>
#include <stdint.h>

// ---------------- problem constants ----------------
#define B_   128
#define N_   100
#define L_   30
#define DF_  2112
#define C_   512
#define T_   4
#define MR_  (B_*N_)          // 12800 rows
#define NEGV (-1e30f)
#define INV_SQRT_C 0.044194173824159216f  // 1/sqrt(512)
#define BIGN (1<<30)

// ---------------- f32 scratch layout ----------------
#define OFF_P1    ((size_t)0)                         // [12800,512]
#define OFF_QCALL (OFF_P1   + (size_t)MR_*C_)         // [128,2048]
#define OFF_GATES (OFF_QCALL+ (size_t)B_*2048)        // [4*128,1536]
#define OFF_BQKV  (OFF_GATES+ (size_t)T_*B_*1536)     // [1536]
#define OFF_BPKPV (OFF_BQKV + 1536)                   // [1024]
#define OFF_BMEMF (OFF_BPKPV+ 1024)                   // [1024] b_mem|b_fuse
#define SCRF_TOTAL (OFF_BMEMF + 1024)
__device__ __align__(16) float g_scratchf[SCRF_TOTAL];

// ---------------- half scratch layout ----------------
#define HO_IMG    ((size_t)0)                          // [12800,2112] normalized
#define HO_XJA    (HO_IMG  + (size_t)MR_*DF_)          // [12800,1536]
#define HO_XJB    (HO_XJA  + (size_t)MR_*1536)         // [12800,1536]
#define HO_QKVB   (HO_XJB  + (size_t)MR_*1536)         // [12800,1536] base (half)
#define HO_QKVF   (HO_QKVB + (size_t)MR_*1536)         // [12800,1536] gated (half)
#define HO_QB     (HO_QKVF + (size_t)MR_*1536)         // [128,512]
#define HO_CMD    (HO_QB   + (size_t)B_*C_)            // [4*128,512]
#define HO_QENC   (HO_CMD  + (size_t)T_*B_*C_)
#define HO_W0     (HO_QENC + (size_t)B_*C_)
// weight block (contiguous, conversion order)
#define HW_INIT   (HO_W0 + 0)
#define HW_QIN    (HO_W0 + 1081344)
#define HW_QIN2   (HO_W0 + 1343488)
#define HW_PLOC   (HO_W0 + 2392064)
#define HW_PCTX   (HO_W0 + 2654208)
#define HW_QKV    (HO_W0 + 2916352)    // Wq|Wk|Wv rows, [1536,1536]
#define HW_PKPV   (HO_W0 + 5275648)    // Wpk|Wpv rows, [1024,512]
#define HW_MEM    (HO_W0 + 5799936)    // [512,1024]
#define HW_COMB   (HO_W0 + 6324224)    // [512,1024]
#define HW_MEMF   (HO_W0 + 6848512)    // [1024,1024]: W_mem ; W_fuse
#define HO_WMT    (HO_W0 + 6848512 + 1048576)  // [1024,512] W_mem^T half
#define SCRH_TOTAL (HO_WMT + 524288)
__device__ __align__(16) __half g_scratchh[SCRH_TOTAL];

// ---------------- generic f32 -> f16 (n % 4 == 0) ----------------
__global__ void f2h_kernel(const float* __restrict__ src, __half* __restrict__ dst, int n4)
{
    int i = blockIdx.x * 256 + threadIdx.x;
    if (i < n4) {
        float4 v = ((const float4*)src)[i];
        __half2 h0 = __floats2half2_rn(v.x, v.y);
        __half2 h1 = __floats2half2_rn(v.z, v.w);
        uint2 o; o.x = *(uint32_t*)&h0; o.y = *(uint32_t*)&h1;
        ((uint2*)dst)[i] = o;
    }
}

// ---------------- merged weight conversion (13 segments) ----------------
#define CW_TOT 1843200
__global__ void convw_kernel(const float* s0, const float* s1, const float* s2,
                             const float* s3, const float* s4, const float* s5,
                             const float* s6, const float* s7, const float* s8,
                             const float* s9, const float* s10, const float* s11,
                             __half* __restrict__ dst)
{
    int i = blockIdx.x * 256 + threadIdx.x;
    if (i >= CW_TOT) return;
    const float* src; int off;
    if      (i < 270336)  { src = s0;  off = i; }
    else if (i < 335872)  { src = s1;  off = i - 270336; }
    else if (i < 598016)  { src = s2;  off = i - 335872; }
    else if (i < 663552)  { src = s3;  off = i - 598016; }
    else if (i < 729088)  { src = s4;  off = i - 663552; }
    else if (i < 925696)  { src = s5;  off = i - 729088; }
    else if (i < 1122304) { src = s6;  off = i - 925696; }
    else if (i < 1318912) { src = s7;  off = i - 1122304; }
    else if (i < 1384448) { src = s8;  off = i - 1318912; }
    else if (i < 1449984) { src = s9;  off = i - 1384448; }
    else if (i < 1581056) { src = s10; off = i - 1449984; }
    else if (i < 1712128) { src = s11; off = i - 1581056; }
    else                  { src = s10; off = i - 1712128; }   // W_mem dup -> HW_MEMF rows 0-511
    float4 v = ((const float4*)src)[off];
    __half2 h0 = __floats2half2_rn(v.x, v.y);
    __half2 h1 = __floats2half2_rn(v.z, v.w);
    uint2 o; o.x = *(uint32_t*)&h0; o.y = *(uint32_t*)&h1;
    ((uint2*)dst)[i] = o;
}

// ---------------- W_mem transpose (f32 [512,1024] -> half [1024,512]) ------
__global__ void wmt_kernel(const float* __restrict__ Wm, __half* __restrict__ out)
{
    int idx = blockIdx.x * 256 + threadIdx.x;   // 524288
    if (idx < 1024 * 512) {
        int j = idx & 511, c = idx >> 9;
        out[idx] = __float2half(Wm[(size_t)j * 1024 + c]);
    }
}

// ---------------- fused bias: bmemf[512+n] = W_pctx[n,:]@b_mem + b_pctx[n] --
__global__ void bfuse_kernel(const float* __restrict__ Wp, const float* __restrict__ bm,
                             const float* __restrict__ bp, float* __restrict__ bmemf)
{
    int n = blockIdx.x * 256 + threadIdx.x;
    if (n < 512) {
        float s = 0.f;
        const float* row = Wp + (size_t)n * 512;
        for (int j = 0; j < 512; j++) s += row[j] * bm[j];
        bmemf[512 + n] = s + bp[n];
    }
}

// ---------------- fused row-normalize + f32->f16 of images ------------------
__global__ void norm_img_kernel(const float* __restrict__ img, __half* __restrict__ dst)
{
    int row = blockIdx.x;
    int tid = threadIdx.x;
    const float4* r = (const float4*)(img + (size_t)row * DF_);  // 528 float4
    float4 v[3];
    float s = 0.f;
#pragma unroll
    for (int j = 0; j < 3; j++) {
        int idx = tid + j * 256;
        if (idx < 528) {
            v[j] = r[idx];
            s += v[j].x * v[j].x + v[j].y * v[j].y + v[j].z * v[j].z + v[j].w * v[j].w;
        }
    }
    __shared__ float red[256];
    red[tid] = s; __syncthreads();
    for (int o = 128; o > 0; o >>= 1) { if (tid < o) red[tid] += red[tid + o]; __syncthreads(); }
    float inv = 1.f / fmaxf(sqrtf(red[0]), 1e-12f);
    uint2* out = (uint2*)(dst + (size_t)row * DF_);
#pragma unroll
    for (int j = 0; j < 3; j++) {
        int idx = tid + j * 256;
        if (idx < 528) {
            __half2 h0 = __floats2half2_rn(v[j].x * inv, v[j].y * inv);
            __half2 h1 = __floats2half2_rn(v[j].z * inv, v[j].w * inv);
            uint2 o; o.x = *(uint32_t*)&h0; o.y = *(uint32_t*)&h1;
            out[idx] = o;
        }
    }
}

// ---------------- setup: init x_ctx slice of xjA + ones gates (vectorized) --
__global__ void setup_kernel(const float* __restrict__ initMem,
                             __half* __restrict__ xjA, float* __restrict__ gates)
{
    int i = blockIdx.x * 256 + threadIdx.x;
    if (i < MR_ * C_ / 8) {
        int m = i >> 6, c8 = (i & 63) * 8;
        float4 a = *(const float4*)(initMem + c8);
        float4 b = *(const float4*)(initMem + c8 + 4);
        __half2 h0 = __floats2half2_rn(a.x, a.y);
        __half2 h1 = __floats2half2_rn(a.z, a.w);
        __half2 h2 = __floats2half2_rn(b.x, b.y);
        __half2 h3 = __floats2half2_rn(b.z, b.w);
        uint4 o;
        o.x = *(uint32_t*)&h0; o.y = *(uint32_t*)&h1;
        o.z = *(uint32_t*)&h2; o.w = *(uint32_t*)&h3;
        *(uint4*)(xjA + (size_t)m * 1536 + 512 + c8) = o;
    }
    if (i < T_ * B_ * C_ / 4) {
        int r = i >> 7, c4 = (i & 127) * 4;
        float4 one = {1.f, 1.f, 1.f, 1.f};
        *(float4*)(gates + (size_t)r * 1536 + c4) = one;
    }
}

// ============================================================================
// FP16 tensor-core NT GEMM: C[m,n] = epi( sum_k A[m,k]*W[n,k] ), f32 accum.
// 128x128 tile, BK=64, 3-stage cp.async, ldmatrix, one sync per k64 iter.
// epilogue: v = acc + bias[nc]; if (accMode==2 && nc<caccN) v += Cacc/CaccH;
//           if (emul && nc>=emulOff) v *= emul[(mr/mdiv)*eld + nc-emulOff];
//           act; if accMode==1 v += Cacc; store Cf / Ch (+Ch2).
// ============================================================================
#define STAGE_B 18432              // 128 rows * 144 B
#define SMB (3*STAGE_B)
#define SM_TOT (6*STAGE_B)         // 110592

__device__ __forceinline__ void cp16(uint32_t dst, const void* src)
{
    asm volatile("cp.async.cg.shared.global [%0], [%1], 16;"
                 :: "r"(dst), "l"(__cvta_generic_to_global(src)) : "memory");
}

__device__ __forceinline__ void ldsm4(uint32_t& r0, uint32_t& r1, uint32_t& r2, uint32_t& r3,
                                      uint32_t addr)
{
    asm volatile("ldmatrix.sync.aligned.m8n8.x4.shared.b16 {%0,%1,%2,%3}, [%4];"
                 : "=r"(r0), "=r"(r1), "=r"(r2), "=r"(r3) : "r"(addr));
}

__global__ void __launch_bounds__(256, 2) gemm_h_kernel(
    const __half* __restrict__ A, int lda,
    const __half* __restrict__ W, int ldw,
    const float* __restrict__ bias,
    const float* __restrict__ emul, int emul_mdiv, int emul_ld, int emulOff,
    float* __restrict__ Cf, __half* __restrict__ Ch, __half* __restrict__ Ch2,
    const float* __restrict__ Cacc, const __half* __restrict__ CaccH,
    int ldacc, int accMode, int caccN,
    int ldc, int K, int act)
{
    extern __shared__ __align__(16) char smem[];
    uint32_t sb;
    asm("{ .reg .u64 t; cvta.to.shared.u64 t, %1; cvt.u32.u64 %0, t; }" : "=r"(sb) : "l"(smem));

    const int tid  = threadIdx.x;
    const int lane = tid & 31;
    const int wid  = tid >> 5;
    const int g    = lane >> 2;
    const int tg   = lane & 3;
    const int wm   = (wid >> 2) * 64;
    const int wn   = (wid & 3) * 32;
    const int mBase = blockIdx.y * 128, nBase = blockIdx.x * 128;

    const __half* gA[4]; const __half* gW[4];
    uint32_t sA[4], sB[4];
#pragma unroll
    for (int j = 0; j < 4; j++) {
        int idx = tid + j * 256;
        int row = idx >> 3, kc = idx & 7;
        gA[j] = A + (size_t)(mBase + row) * lda + kc * 8;
        gW[j] = W + (size_t)(nBase + row) * ldw + kc * 8;
        sA[j] = sb + row * 144 + kc * 16;
        sB[j] = sb + SMB + row * 144 + kc * 16;
    }

    uint32_t aoff[4], boff[2];
    {
        int r16 = lane & 15, kh = lane >> 4;
#pragma unroll
        for (int ma = 0; ma < 4; ma++)
            aoff[ma] = sb + (wm + ma * 16 + r16) * 144 + kh * 16;
        int br = ((lane >> 3) & 1) * 8 + (lane & 7);
#pragma unroll
        for (int nb = 0; nb < 2; nb++)
            boff[nb] = sb + SMB + (wn + nb * 16 + br) * 144 + kh * 16;
    }

    float acc[4][4][4];
#pragma unroll
    for (int i = 0; i < 4; i++)
#pragma unroll
        for (int j = 0; j < 4; j++)
#pragma unroll
            for (int r = 0; r < 4; r++) acc[i][j][r] = 0.f;

    const int nk = K >> 6;
#pragma unroll
    for (int s = 0; s < 2; s++) {
        if (s < nk) {
            int ko = s << 6;
#pragma unroll
            for (int j = 0; j < 4; j++) {
                cp16(sA[j] + s * STAGE_B, gA[j] + ko);
                cp16(sB[j] + s * STAGE_B, gW[j] + ko);
            }
        }
        asm volatile("cp.async.commit_group;" ::: "memory");
    }

    for (int k = 0; k < nk; ++k) {
        asm volatile("cp.async.wait_group 1;" ::: "memory");
        __syncthreads();
        if (k + 2 < nk) {
            int s = (k + 2) % 3;
            int ko = (k + 2) << 6;
#pragma unroll
            for (int j = 0; j < 4; j++) {
                cp16(sA[j] + s * STAGE_B, gA[j] + ko);
                cp16(sB[j] + s * STAGE_B, gW[j] + ko);
            }
        }
        asm volatile("cp.async.commit_group;" ::: "memory");

        const uint32_t st = (k % 3) * STAGE_B;
#pragma unroll
        for (int sub = 0; sub < 4; sub++) {
            const uint32_t kb = st + sub * 32;
            uint32_t af[4][4], bf[4][2];
#pragma unroll
            for (int ma = 0; ma < 4; ma++)
                ldsm4(af[ma][0], af[ma][1], af[ma][2], af[ma][3], aoff[ma] + kb);
#pragma unroll
            for (int nb = 0; nb < 2; nb++) {
                uint32_t b0, b1, b2, b3;
                ldsm4(b0, b1, b2, b3, boff[nb] + kb);
                bf[2 * nb][0] = b0; bf[2 * nb + 1][0] = b1;
                bf[2 * nb][1] = b2; bf[2 * nb + 1][1] = b3;
            }
#pragma unroll
            for (int ma = 0; ma < 4; ma++)
#pragma unroll
                for (int na = 0; na < 4; na++) {
                    asm volatile(
                        "mma.sync.aligned.m16n8k16.row.col.f32.f16.f16.f32 "
                        "{%0,%1,%2,%3}, {%4,%5,%6,%7}, {%8,%9}, {%0,%1,%2,%3};"
                        : "+f"(acc[ma][na][0]), "+f"(acc[ma][na][1]),
                          "+f"(acc[ma][na][2]), "+f"(acc[ma][na][3])
                        : "r"(af[ma][0]), "r"(af[ma][1]), "r"(af[ma][2]), "r"(af[ma][3]),
                          "r"(bf[na][0]), "r"(bf[na][1]));
                }
        }
    }

    // -------- epilogue --------
#pragma unroll
    for (int ma = 0; ma < 4; ma++) {
#pragma unroll
        for (int half = 0; half < 2; half++) {
            int mr = mBase + wm + ma * 16 + g + half * 8;
            const float* em = emul ? (emul + (size_t)(mr / emul_mdiv) * emul_ld) : (const float*)0;
#pragma unroll
            for (int na = 0; na < 4; na++) {
                int nc = nBase + wn + na * 8 + 2 * tg;
                float v0 = acc[ma][na][half * 2 + 0];
                float v1 = acc[ma][na][half * 2 + 1];
                if (bias) { v0 += bias[nc]; v1 += bias[nc + 1]; }
                if (accMode == 2 && nc < caccN) {
                    if (CaccH) {
                        __half2 o = *(const __half2*)(CaccH + (size_t)mr * ldacc + nc);
                        float2 f = __half22float2(o);
                        v0 += f.x; v1 += f.y;
                    } else {
                        float2 o = *(const float2*)(Cacc + (size_t)mr * ldacc + nc);
                        v0 += o.x; v1 += o.y;
                    }
                }
                if (em && nc >= emulOff) {
                    v0 *= em[nc - emulOff];
                    v1 *= em[nc + 1 - emulOff];
                }
                if (act) {
                    v0 = (v0 > 0.f) ? v0 : expm1f(v0);
                    v1 = (v1 > 0.f) ? v1 : expm1f(v1);
                }
                if (accMode == 1) {
                    float2 o = *(const float2*)(Cacc + (size_t)mr * ldacc + nc);
                    v0 += o.x; v1 += o.y;
                }
                if (Cf) {
                    float2 ov = {v0, v1};
                    *(float2*)(Cf + (size_t)mr * ldc + nc) = ov;
                }
                if (Ch) {
                    __half2 hv = __floats2half2_rn(v0, v1);
                    *(__half2*)(Ch + (size_t)mr * ldc + nc) = hv;
                    if (Ch2) *(__half2*)(Ch2 + (size_t)mr * ldc + nc) = hv;
                }
            }
        }
    }
}

// ---------------- command attention (all T at once) -------------------------
__global__ void cmd_attn_all_kernel(const float* __restrict__ qcall,
                                    const float* __restrict__ lstm,
                                    const float* __restrict__ Wl,
                                    const float* __restrict__ bl,
                                    const int* __restrict__ qlen,
                                    __half* __restrict__ cmdh)
{
    int b = blockIdx.x, t = blockIdx.y;
    int tid = threadIdx.x, lane = tid & 31, wid = tid >> 5;
    __shared__ float qw[C_];
    __shared__ float att[32];
    const float* qcmd = qcall + (size_t)b * 2048 + t * C_;
    for (int c = tid; c < C_; c += 256) qw[c] = qcmd[c] * Wl[c];
    __syncthreads();
    for (int l = wid; l < L_; l += 8) {
        const float* lr = lstm + ((size_t)b * L_ + l) * C_;
        float s = 0.f;
        for (int c = lane; c < C_; c += 32) s += qw[c] * lr[c];
        for (int o = 16; o; o >>= 1) s += __shfl_xor_sync(0xffffffffu, s, o);
        if (lane == 0) att[l] = s + bl[0];
    }
    __syncthreads();
    if (tid == 0) {
        int Lq = qlen[b];
        float mx = NEGV;
        for (int l = 0; l < Lq; l++) mx = fmaxf(mx, att[l]);
        float sum = 0.f;
        for (int l = 0; l < Lq; l++) { float e = expf(att[l] - mx); att[l] = e; sum += e; }
        float invs = 1.f / sum;
        for (int l = 0; l < Lq; l++) att[l] *= invs;
        for (int l = Lq; l < L_; l++) att[l] = 0.f;
    }
    __syncthreads();
    __half* outr = cmdh + (size_t)(t * B_ + b) * C_;
    for (int c = tid; c < C_; c += 256) {
        float s = 0.f;
#pragma unroll 5
        for (int l = 0; l < L_; l++) s += att[l] * lstm[((size_t)b * L_ + l) * C_ + c];
        outr[c] = __float2half(s);
    }
}

// ---------------- fused entity attention ------------------------------------
#define QC 10
#define QS 1536

__device__ __forceinline__ float4 h4f(uint2 v)
{
    __half2* hp = (__half2*)&v;
    float2 f0 = __half22float2(hp[0]);
    float2 f1 = __half22float2(hp[1]);
    float4 o = {f0.x, f0.y, f1.x, f1.y};
    return o;
}

__global__ void ent_attn_kernel(const __half* __restrict__ QKV,
                                const int* __restrict__ entnum,
                                __half* __restrict__ xj_msg)
{
    int b = blockIdx.x, qc = blockIdx.y;
    int tid = threadIdx.x, lane = tid & 31, wid = tid >> 5;
    __shared__ uint32_t Qh[QC * 260];
    __shared__ float Ps[QC * 104];

    for (int i = tid; i < QC * 128; i += 256) {
        int r = i >> 7, c4 = i & 127;
        uint2 v = *(const uint2*)(QKV + ((size_t)(b * N_ + qc * QC + r)) * QS + c4 * 4);
        *(uint2*)&Qh[r * 260 + c4 * 2] = v;
    }
    __syncthreads();
    int en = entnum[b];

    for (int k0 = wid * 2; k0 < N_; k0 += 16) {
        const __half* kr0 = QKV + ((size_t)(b * N_ + k0)) * QS + 512;
        const __half* kr1 = kr0 + QS;
        float a0[QC], a1[QC];
#pragma unroll
        for (int q = 0; q < QC; q++) { a0[q] = 0.f; a1[q] = 0.f; }
#pragma unroll
        for (int t = 0; t < 4; t++) {
            float4 f0 = h4f(*(const uint2*)(kr0 + lane * 4 + t * 128));
            float4 f1 = h4f(*(const uint2*)(kr1 + lane * 4 + t * 128));
#pragma unroll
            for (int q = 0; q < QC; q++) {
                float4 qf = h4f(*(const uint2*)&Qh[q * 260 + lane * 2 + t * 64]);
                a0[q] += qf.x * f0.x + qf.y * f0.y + qf.z * f0.z + qf.w * f0.w;
                a1[q] += qf.x * f1.x + qf.y * f1.y + qf.z * f1.z + qf.w * f1.w;
            }
        }
#pragma unroll
        for (int q = 0; q < QC; q++) {
            for (int o = 16; o; o >>= 1) {
                a0[q] += __shfl_xor_sync(0xffffffffu, a0[q], o);
                a1[q] += __shfl_xor_sync(0xffffffffu, a1[q], o);
            }
        }
        if (lane == 0) {
#pragma unroll
            for (int q = 0; q < QC; q++) {
                Ps[q * 104 + k0]     = (k0 < en)     ? a0[q] * INV_SQRT_C : NEGV;
                Ps[q * 104 + k0 + 1] = (k0 + 1 < en) ? a1[q] * INV_SQRT_C : NEGV;
            }
        }
    }
    __syncthreads();

    for (int r = wid; r < QC; r += 8) {
        float v[4];
#pragma unroll
        for (int t = 0; t < 4; t++) {
            int c = lane + t * 32;
            v[t] = (c < N_) ? Ps[r * 104 + c] : NEGV;
        }
        float mx = fmaxf(fmaxf(v[0], v[1]), fmaxf(v[2], v[3]));
        for (int o = 16; o; o >>= 1) mx = fmaxf(mx, __shfl_xor_sync(0xffffffffu, mx, o));
        float sum = 0.f, e[4];
#pragma unroll
        for (int t = 0; t < 4; t++) { e[t] = expf(v[t] - mx); sum += e[t]; }
        for (int o = 16; o; o >>= 1) sum += __shfl_xor_sync(0xffffffffu, sum, o);
        float invs = 1.f / sum;
#pragma unroll
        for (int t = 0; t < 4; t++) {
            int c = lane + t * 32;
            if (c < N_) Ps[r * 104 + c] = e[t] * invs;
        }
    }
    __syncthreads();

    const __half* Vb = QKV + (size_t)(b * N_) * QS + 1024;
    int c0 = tid, c1 = tid + 256;
    float acc0[QC], acc1[QC];
#pragma unroll
    for (int q = 0; q < QC; q++) { acc0[q] = 0.f; acc1[q] = 0.f; }
#pragma unroll 4
    for (int k = 0; k < N_; k++) {
        float v0 = __half2float(Vb[(size_t)k * QS + c0]);
        float v1 = __half2float(Vb[(size_t)k * QS + c1]);
#pragma unroll
        for (int q = 0; q < QC; q++) {
            float p = Ps[q * 104 + k];
            acc0[q] += p * v0;
            acc1[q] += p * v1;
        }
    }
#pragma unroll
    for (int q = 0; q < QC; q++) {
        size_t row = (size_t)(b * N_ + qc * QC + q);
        xj_msg[row * 1536 + 1024 + c0] = __float2half(acc0[q]);
        xj_msg[row * 1536 + 1024 + c1] = __float2half(acc1[q]);
    }
}

// ---------------- host helpers ----------------
static inline void gemm(const __half* A, int lda, const __half* W, int ldw,
                        const float* bias,
                        const float* emul, int mdiv, int eld, int emulOff,
                        float* Cf, __half* Ch, __half* Ch2,
                        const float* Cacc, const __half* CaccH, int ldacc,
                        int accMode, int caccN,
                        int ldc, int M, int N, int K, int act)
{
    dim3 grid(N / 128, M / 128);
    gemm_h_kernel<<<grid, 256, SM_TOT>>>(A, lda, W, ldw, bias,
                                         emul, mdiv > 0 ? mdiv : 1, eld, emulOff,
                                         Cf, Ch, Ch2, Cacc, CaccH, ldacc, accMode, caccN,
                                         ldc, K, act);
}

extern "C" void kernel_launch(void* const* d_in, const int* in_sizes, int n_in,
                              void* d_out, int out_size)
{
    const float* images     = (const float*)d_in[0];
    const float* q_encoding = (const float*)d_in[1];
    const float* lstm       = (const float*)d_in[2];
    const float* W_initKB   = (const float*)d_in[3];
    const float* b_initKB   = (const float*)d_in[4];
    const float* initMem    = (const float*)d_in[5];
    const float* W_qIn      = (const float*)d_in[6];
    const float* b_qIn      = (const float*)d_in[7];
    const float* W_qIn2     = (const float*)d_in[8];
    const float* b_qIn2     = (const float*)d_in[9];
    const float* W_logit    = (const float*)d_in[10];
    const float* b_logit    = (const float*)d_in[11];
    const float* W_ploc     = (const float*)d_in[12];
    const float* b_ploc     = (const float*)d_in[13];
    const float* W_pctx     = (const float*)d_in[14];
    const float* b_pctx     = (const float*)d_in[15];
    const float* W_q        = (const float*)d_in[16];
    const float* b_q        = (const float*)d_in[17];
    const float* W_k        = (const float*)d_in[18];
    const float* b_k        = (const float*)d_in[19];
    const float* W_v        = (const float*)d_in[20];
    const float* b_v        = (const float*)d_in[21];
    const float* W_pk       = (const float*)d_in[22];
    const float* b_pk       = (const float*)d_in[23];
    const float* W_pv       = (const float*)d_in[24];
    const float* b_pv       = (const float*)d_in[25];
    const float* W_mem      = (const float*)d_in[26];
    const float* b_mem      = (const float*)d_in[27];
    const float* W_comb     = (const float*)d_in[28];
    const float* b_comb     = (const float*)d_in[29];
    const int*   q_length   = (const int*)d_in[30];
    const int*   entity_num = (const int*)d_in[31];

    cudaFuncSetAttribute(gemm_h_kernel, cudaFuncAttributeMaxDynamicSharedMemorySize, SM_TOT);

    float* Sf = 0;  __half* Sh = 0;
    cudaGetSymbolAddress((void**)&Sf, g_scratchf);
    cudaGetSymbolAddress((void**)&Sh, g_scratchh);

    float* P1    = Sf + OFF_P1;
    float* qcall = Sf + OFF_QCALL;
    float* gates = Sf + OFF_GATES;
    float* bqkv  = Sf + OFF_BQKV;
    float* bpkpv = Sf + OFF_BPKPV;
    float* bmemf = Sf + OFF_BMEMF;
    float* outp  = (float*)d_out;

    __half* imgh  = Sh + HO_IMG;
    __half* xjA   = Sh + HO_XJA;
    __half* xjB   = Sh + HO_XJB;
    __half* QKVbh = Sh + HO_QKVB;
    __half* QKVfh = Sh + HO_QKVF;
    __half* qbh   = Sh + HO_QB;
    __half* cmdh  = Sh + HO_CMD;
    __half* qeh   = Sh + HO_QENC;

    // ---- conversions + bias buffers + fused weight build ----
    convw_kernel<<<(CW_TOT + 255) / 256, 256>>>(
        W_initKB, W_qIn, W_qIn2, W_ploc, W_pctx,
        W_q, W_k, W_v, W_pk, W_pv, W_mem, W_comb, Sh + HO_W0);
    norm_img_kernel<<<MR_, 256>>>(images, imgh);
    {
        int n4 = B_ * C_ / 4;
        f2h_kernel<<<(n4 + 255) / 256, 256>>>(q_encoding, qeh, n4);
    }
    wmt_kernel<<<(1024 * 512 + 255) / 256, 256>>>(W_mem, Sh + HO_WMT);
    // W_fuse = W_pctx @ W_mem  -> HW_MEMF rows 512-1023 (half)
    gemm(Sh + HW_PCTX, 512, Sh + HO_WMT, 512, 0, 0, 1, 0, 0,
         0, Sh + HW_MEMF + 512 * 1024, 0, 0, 0, 0, 0, BIGN,
         1024, 512, 1024, 512, 0);
    bfuse_kernel<<<2, 256>>>(W_pctx, b_mem, b_pctx, bmemf);
    cudaMemcpyAsync(bmemf,       b_mem, C_ * 4, cudaMemcpyDeviceToDevice);
    cudaMemcpyAsync(bqkv,        b_q,  C_ * 4, cudaMemcpyDeviceToDevice);
    cudaMemcpyAsync(bqkv + C_,   b_k,  C_ * 4, cudaMemcpyDeviceToDevice);
    cudaMemcpyAsync(bqkv + 2*C_, b_v,  C_ * 4, cudaMemcpyDeviceToDevice);
    cudaMemcpyAsync(bpkpv,       b_pk, C_ * 4, cudaMemcpyDeviceToDevice);
    cudaMemcpyAsync(bpkpv + C_,  b_pv, C_ * 4, cudaMemcpyDeviceToDevice);

    // ---- stem + setup ----
    setup_kernel<<<(MR_ * C_ / 8 + 255) / 256, 256>>>(initMem, xjA, gates);
    gemm(imgh, DF_, Sh + HW_INIT, DF_, b_initKB, 0, 1, 0, 0,
         0, xjA, xjB, 0, 0, 0, 0, BIGN, 1536, MR_, C_, DF_, 0);  // x_loc -> xjA & xjB

    // ---- loop-invariant precomputes ----
    gemm(xjA, 1536, Sh + HW_PLOC, C_, b_ploc, 0, 1, 0, 0,
         P1, 0, 0, 0, 0, 0, 0, BIGN, C_, MR_, C_, C_, 0);
    gemm(xjA, 1536, Sh + HW_QKV, 1536, bqkv, 0, 1, 0, 0,
         0, QKVbh, 0, 0, 0, 0, 0, BIGN, 1536, MR_, 1536, C_, 0);

    // ---- command pipeline (all T upfront) ----
    gemm(qeh, C_, Sh + HW_QIN, C_, b_qIn, 0, 1, 0, 0,
         0, qbh, 0, 0, 0, 0, 0, BIGN, C_, B_, C_, C_, 1);
    gemm(qbh, C_, Sh + HW_QIN2, C_, b_qIn2, 0, 1, 0, 0,
         qcall, 0, 0, 0, 0, 0, 0, BIGN, 2048, B_, 2048, C_, 0);
    cmd_attn_all_kernel<<<dim3(B_, T_), 256>>>(qcall, lstm, W_logit, b_logit, q_length, cmdh);
    gemm(cmdh, C_, Sh + HW_PKPV, C_, bpkpv, 0, 1, 0, 0,
         gates + 512, 0, 0, 0, 0, 0, 0, BIGN, 1536, T_ * B_, 1024, C_, 0);

    // ---- prologue: initial prod for t=0 -> xjA[:,1024:1536] ----
    gemm(xjA + 512, 1536, Sh + HW_PCTX, C_, b_pctx, P1, 1, C_, 0,
         0, xjA + 1024, 0, 0, 0, 0, 0, BIGN, 1536, MR_, C_, C_, 0);

    for (int t = 0; t < T_; t++) {
        __half* cur = (t & 1) ? xjB : xjA;
        __half* nxt = (t & 1) ? xjA : xjB;

        // QKV = (partial(x_ctx|prod) + base_h) * gates  -> half
        gemm(cur + 512, 1536, Sh + HW_QKV + 512, 1536, 0,
             gates + (size_t)t * B_ * 1536, N_, 1536, 0,
             0, QKVfh, 0, 0, QKVbh, 1536, 2, BIGN,
             1536, MR_, 1536, 1024, 0);

        // fused entity attention -> msg into cur[:,1024:1536] (prod consumed)
        ent_attn_kernel<<<dim3(B_, N_ / QC), 256>>>(QKVfh, entity_num, cur);

        // [x_ctx', prod'] = [x_ctx,msg] @ [W_mem ; W_fuse]^T + bmemf,
        // cols 512-1023 *= P1  -> nxt[:,512:1536]
        gemm(cur + 512, 1536, Sh + HW_MEMF, 1024, bmemf,
             P1, 1, C_, 512,
             0, nxt + 512, 0, 0, 0, 0, 0, BIGN,
             1536, MR_, 1024, 1024, 0);
    }

    // out = Linear([x_loc, x_ctx])  (xjA holds both contiguously)
    gemm(xjA, 1536, Sh + HW_COMB, 2 * C_, b_comb, 0, 1, 0, 0,
         outp, 0, 0, 0, 0, 0, 0, BIGN, C_, MR_, C_, 1024, 0);

    (void)in_sizes; (void)n_in; (void)out_size;
}

// round 15
// speedup vs baseline: 1.1103x; 1.1103x over previous
#include <cuda_runtime.h>
#include <cuda_fp16.h>
#include <math.h>
#include <stdint.h>

// ---------------- problem constants ----------------
#define B_   128
#define N_   100
#define L_   30
#define DF_  2112
#define C_   512
#define T_   4
#define MR_  (B_*N_)          // 12800 rows
#define NEGV (-1e30f)
#define INV_SQRT_C 0.044194173824159216f  // 1/sqrt(512)

// ---------------- f32 scratch layout ----------------
#define OFF_P1    ((size_t)0)                         // [12800,512]
#define OFF_QCALL (OFF_P1   + (size_t)MR_*C_)         // [128,2048]
#define OFF_GATES (OFF_QCALL+ (size_t)B_*2048)        // [4*128,1536]
#define OFF_BQKV  (OFF_GATES+ (size_t)T_*B_*1536)     // [1536]
#define OFF_BPKPV (OFF_BQKV + 1536)                   // [1024]
#define SCRF_TOTAL (OFF_BPKPV + 1024)
__device__ __align__(16) float g_scratchf[SCRF_TOTAL];

// ---------------- half scratch layout ----------------
#define HO_IMG    ((size_t)0)                          // [12800,2112] normalized
#define HO_XJA    (HO_IMG  + (size_t)MR_*DF_)          // [12800,1536]
#define HO_XJB    (HO_XJA  + (size_t)MR_*1536)         // [12800,1536]
#define HO_QKVB   (HO_XJB  + (size_t)MR_*1536)         // [12800,1536] base (half)
#define HO_QKVF   (HO_QKVB + (size_t)MR_*1536)         // [12800,1536] gated (half)
#define HO_QB     (HO_QKVF + (size_t)MR_*1536)         // [128,512]
#define HO_CMD    (HO_QB   + (size_t)B_*C_)            // [4*128,512]
#define HO_QENC   (HO_CMD  + (size_t)T_*B_*C_)
#define HO_W0     (HO_QENC + (size_t)B_*C_)
// weight block (contiguous, conversion order)
#define HW_INIT   (HO_W0 + 0)
#define HW_QIN    (HO_W0 + 1081344)
#define HW_QIN2   (HO_W0 + 1343488)
#define HW_PLOC   (HO_W0 + 2392064)
#define HW_PCTX   (HO_W0 + 2654208)
#define HW_QKV    (HO_W0 + 2916352)    // Wq|Wk|Wv rows, [1536,1536]
#define HW_PKPV   (HO_W0 + 5275648)    // Wpk|Wpv rows, [1024,512]
#define HW_MEM    (HO_W0 + 5799936)    // [512,1024]
#define HW_COMB   (HO_W0 + 6324224)    // [512,1024]
#define SCRH_TOTAL (HO_W0 + 6848512)
__device__ __align__(16) __half g_scratchh[SCRH_TOTAL];

// ---------------- generic f32 -> f16 (n % 4 == 0) ----------------
__global__ void f2h_kernel(const float* __restrict__ src, __half* __restrict__ dst, int n4)
{
    int i = blockIdx.x * 256 + threadIdx.x;
    if (i < n4) {
        float4 v = ((const float4*)src)[i];
        __half2 h0 = __floats2half2_rn(v.x, v.y);
        __half2 h1 = __floats2half2_rn(v.z, v.w);
        uint2 o; o.x = *(uint32_t*)&h0; o.y = *(uint32_t*)&h1;
        ((uint2*)dst)[i] = o;
    }
}

// ---------------- merged weight conversion (12 segments) ----------------
#define CW_TOT 1712128
__global__ void convw_kernel(const float* s0, const float* s1, const float* s2,
                             const float* s3, const float* s4, const float* s5,
                             const float* s6, const float* s7, const float* s8,
                             const float* s9, const float* s10, const float* s11,
                             __half* __restrict__ dst)
{
    int i = blockIdx.x * 256 + threadIdx.x;
    if (i >= CW_TOT) return;
    const float* src; int off;
    if      (i < 270336)  { src = s0;  off = i; }
    else if (i < 335872)  { src = s1;  off = i - 270336; }
    else if (i < 598016)  { src = s2;  off = i - 335872; }
    else if (i < 663552)  { src = s3;  off = i - 598016; }
    else if (i < 729088)  { src = s4;  off = i - 663552; }
    else if (i < 925696)  { src = s5;  off = i - 729088; }
    else if (i < 1122304) { src = s6;  off = i - 925696; }
    else if (i < 1318912) { src = s7;  off = i - 1122304; }
    else if (i < 1384448) { src = s8;  off = i - 1318912; }
    else if (i < 1449984) { src = s9;  off = i - 1384448; }
    else if (i < 1581056) { src = s10; off = i - 1449984; }
    else                  { src = s11; off = i - 1581056; }
    float4 v = ((const float4*)src)[off];
    __half2 h0 = __floats2half2_rn(v.x, v.y);
    __half2 h1 = __floats2half2_rn(v.z, v.w);
    uint2 o; o.x = *(uint32_t*)&h0; o.y = *(uint32_t*)&h1;
    ((uint2*)dst)[i] = o;
}

// ---------------- fused row-normalize + f32->f16 of images ------------------
__global__ void norm_img_kernel(const float* __restrict__ img, __half* __restrict__ dst)
{
    int row = blockIdx.x;
    int tid = threadIdx.x;
    const float4* r = (const float4*)(img + (size_t)row * DF_);  // 528 float4
    float4 v[3];
    float s = 0.f;
#pragma unroll
    for (int j = 0; j < 3; j++) {
        int idx = tid + j * 256;
        if (idx < 528) {
            v[j] = r[idx];
            s += v[j].x * v[j].x + v[j].y * v[j].y + v[j].z * v[j].z + v[j].w * v[j].w;
        }
    }
    __shared__ float red[256];
    red[tid] = s; __syncthreads();
    for (int o = 128; o > 0; o >>= 1) { if (tid < o) red[tid] += red[tid + o]; __syncthreads(); }
    float inv = 1.f / fmaxf(sqrtf(red[0]), 1e-12f);
    uint2* out = (uint2*)(dst + (size_t)row * DF_);
#pragma unroll
    for (int j = 0; j < 3; j++) {
        int idx = tid + j * 256;
        if (idx < 528) {
            __half2 h0 = __floats2half2_rn(v[j].x * inv, v[j].y * inv);
            __half2 h1 = __floats2half2_rn(v[j].z * inv, v[j].w * inv);
            uint2 o; o.x = *(uint32_t*)&h0; o.y = *(uint32_t*)&h1;
            out[idx] = o;
        }
    }
}

// ---------------- setup: init x_ctx slice of xjA + ones gates (vectorized) --
__global__ void setup_kernel(const float* __restrict__ initMem,
                             __half* __restrict__ xjA, float* __restrict__ gates)
{
    int i = blockIdx.x * 256 + threadIdx.x;
    if (i < MR_ * C_ / 8) {
        int m = i >> 6, c8 = (i & 63) * 8;
        float4 a = *(const float4*)(initMem + c8);
        float4 b = *(const float4*)(initMem + c8 + 4);
        __half2 h0 = __floats2half2_rn(a.x, a.y);
        __half2 h1 = __floats2half2_rn(a.z, a.w);
        __half2 h2 = __floats2half2_rn(b.x, b.y);
        __half2 h3 = __floats2half2_rn(b.z, b.w);
        uint4 o;
        o.x = *(uint32_t*)&h0; o.y = *(uint32_t*)&h1;
        o.z = *(uint32_t*)&h2; o.w = *(uint32_t*)&h3;
        *(uint4*)(xjA + (size_t)m * 1536 + 512 + c8) = o;
    }
    if (i < T_ * B_ * C_ / 4) {
        int r = i >> 7, c4 = (i & 127) * 4;
        float4 one = {1.f, 1.f, 1.f, 1.f};
        *(float4*)(gates + (size_t)r * 1536 + c4) = one;
    }
}

// ============================================================================
// FP16 tensor-core NT GEMM: C[m,n] = epi( sum_k A[m,k]*W[n,k] ), f32 accum.
// 128x128 tile, BK=64, 3-stage cp.async, ldmatrix, one sync per k64 iter.
// (round-12 proven configuration)
// ============================================================================
#define STAGE_B 18432              // 128 rows * 144 B
#define SMB (3*STAGE_B)
#define SM_TOT (6*STAGE_B)         // 110592

__device__ __forceinline__ void cp16(uint32_t dst, const void* src)
{
    asm volatile("cp.async.cg.shared.global [%0], [%1], 16;"
                 :: "r"(dst), "l"(__cvta_generic_to_global(src)) : "memory");
}

__device__ __forceinline__ void ldsm4(uint32_t& r0, uint32_t& r1, uint32_t& r2, uint32_t& r3,
                                      uint32_t addr)
{
    asm volatile("ldmatrix.sync.aligned.m8n8.x4.shared.b16 {%0,%1,%2,%3}, [%4];"
                 : "=r"(r0), "=r"(r1), "=r"(r2), "=r"(r3) : "r"(addr));
}

__global__ void __launch_bounds__(256, 2) gemm_h_kernel(
    const __half* __restrict__ A, int lda,
    const __half* __restrict__ W, int ldw,
    const float* __restrict__ bias,
    const float* __restrict__ emul, int emul_mdiv, int emul_ld,
    float* __restrict__ Cf, __half* __restrict__ Ch, __half* __restrict__ Ch2,
    const float* __restrict__ Cacc, const __half* __restrict__ CaccH,
    int ldacc, int accMode,
    int ldc, int K, int act)
{
    extern __shared__ __align__(16) char smem[];
    uint32_t sb;
    asm("{ .reg .u64 t; cvta.to.shared.u64 t, %1; cvt.u32.u64 %0, t; }" : "=r"(sb) : "l"(smem));

    const int tid  = threadIdx.x;
    const int lane = tid & 31;
    const int wid  = tid >> 5;
    const int g    = lane >> 2;
    const int tg   = lane & 3;
    const int wm   = (wid >> 2) * 64;
    const int wn   = (wid & 3) * 32;
    const int mBase = blockIdx.y * 128, nBase = blockIdx.x * 128;

    const __half* gA[4]; const __half* gW[4];
    uint32_t sA[4], sB[4];
#pragma unroll
    for (int j = 0; j < 4; j++) {
        int idx = tid + j * 256;
        int row = idx >> 3, kc = idx & 7;
        gA[j] = A + (size_t)(mBase + row) * lda + kc * 8;
        gW[j] = W + (size_t)(nBase + row) * ldw + kc * 8;
        sA[j] = sb + row * 144 + kc * 16;
        sB[j] = sb + SMB + row * 144 + kc * 16;
    }

    uint32_t aoff[4], boff[2];
    {
        int r16 = lane & 15, kh = lane >> 4;
#pragma unroll
        for (int ma = 0; ma < 4; ma++)
            aoff[ma] = sb + (wm + ma * 16 + r16) * 144 + kh * 16;
        int br = ((lane >> 3) & 1) * 8 + (lane & 7);
#pragma unroll
        for (int nb = 0; nb < 2; nb++)
            boff[nb] = sb + SMB + (wn + nb * 16 + br) * 144 + kh * 16;
    }

    float acc[4][4][4];
#pragma unroll
    for (int i = 0; i < 4; i++)
#pragma unroll
        for (int j = 0; j < 4; j++)
#pragma unroll
            for (int r = 0; r < 4; r++) acc[i][j][r] = 0.f;

    const int nk = K >> 6;
#pragma unroll
    for (int s = 0; s < 2; s++) {
        if (s < nk) {
            int ko = s << 6;
#pragma unroll
            for (int j = 0; j < 4; j++) {
                cp16(sA[j] + s * STAGE_B, gA[j] + ko);
                cp16(sB[j] + s * STAGE_B, gW[j] + ko);
            }
        }
        asm volatile("cp.async.commit_group;" ::: "memory");
    }

    for (int k = 0; k < nk; ++k) {
        asm volatile("cp.async.wait_group 1;" ::: "memory");
        __syncthreads();
        if (k + 2 < nk) {
            int s = (k + 2) % 3;
            int ko = (k + 2) << 6;
#pragma unroll
            for (int j = 0; j < 4; j++) {
                cp16(sA[j] + s * STAGE_B, gA[j] + ko);
                cp16(sB[j] + s * STAGE_B, gW[j] + ko);
            }
        }
        asm volatile("cp.async.commit_group;" ::: "memory");

        const uint32_t st = (k % 3) * STAGE_B;
#pragma unroll
        for (int sub = 0; sub < 4; sub++) {
            const uint32_t kb = st + sub * 32;
            uint32_t af[4][4], bf[4][2];
#pragma unroll
            for (int ma = 0; ma < 4; ma++)
                ldsm4(af[ma][0], af[ma][1], af[ma][2], af[ma][3], aoff[ma] + kb);
#pragma unroll
            for (int nb = 0; nb < 2; nb++) {
                uint32_t b0, b1, b2, b3;
                ldsm4(b0, b1, b2, b3, boff[nb] + kb);
                bf[2 * nb][0] = b0; bf[2 * nb + 1][0] = b1;
                bf[2 * nb][1] = b2; bf[2 * nb + 1][1] = b3;
            }
#pragma unroll
            for (int ma = 0; ma < 4; ma++)
#pragma unroll
                for (int na = 0; na < 4; na++) {
                    asm volatile(
                        "mma.sync.aligned.m16n8k16.row.col.f32.f16.f16.f32 "
                        "{%0,%1,%2,%3}, {%4,%5,%6,%7}, {%8,%9}, {%0,%1,%2,%3};"
                        : "+f"(acc[ma][na][0]), "+f"(acc[ma][na][1]),
                          "+f"(acc[ma][na][2]), "+f"(acc[ma][na][3])
                        : "r"(af[ma][0]), "r"(af[ma][1]), "r"(af[ma][2]), "r"(af[ma][3]),
                          "r"(bf[na][0]), "r"(bf[na][1]));
                }
        }
    }

    // -------- epilogue --------
#pragma unroll
    for (int ma = 0; ma < 4; ma++) {
#pragma unroll
        for (int half = 0; half < 2; half++) {
            int mr = mBase + wm + ma * 16 + g + half * 8;
            const float* em = emul ? (emul + (size_t)(mr / emul_mdiv) * emul_ld) : (const float*)0;
#pragma unroll
            for (int na = 0; na < 4; na++) {
                int nc = nBase + wn + na * 8 + 2 * tg;
                float v0 = acc[ma][na][half * 2 + 0];
                float v1 = acc[ma][na][half * 2 + 1];
                if (bias) { v0 += bias[nc]; v1 += bias[nc + 1]; }
                if (accMode == 2) {
                    if (CaccH) {
                        __half2 o = *(const __half2*)(CaccH + (size_t)mr * ldacc + nc);
                        float2 f = __half22float2(o);
                        v0 += f.x; v1 += f.y;
                    } else {
                        float2 o = *(const float2*)(Cacc + (size_t)mr * ldacc + nc);
                        v0 += o.x; v1 += o.y;
                    }
                }
                if (em)   { v0 *= em[nc];   v1 *= em[nc + 1]; }
                if (act)  {
                    v0 = (v0 > 0.f) ? v0 : expm1f(v0);
                    v1 = (v1 > 0.f) ? v1 : expm1f(v1);
                }
                if (accMode == 1) {
                    float2 o = *(const float2*)(Cacc + (size_t)mr * ldacc + nc);
                    v0 += o.x; v1 += o.y;
                }
                if (Cf) {
                    float2 ov = {v0, v1};
                    *(float2*)(Cf + (size_t)mr * ldc + nc) = ov;
                }
                if (Ch) {
                    __half2 hv = __floats2half2_rn(v0, v1);
                    *(__half2*)(Ch + (size_t)mr * ldc + nc) = hv;
                    if (Ch2) *(__half2*)(Ch2 + (size_t)mr * ldc + nc) = hv;
                }
            }
        }
    }
}

// ---------------- command attention (all T at once) -------------------------
__global__ void cmd_attn_all_kernel(const float* __restrict__ qcall,
                                    const float* __restrict__ lstm,
                                    const float* __restrict__ Wl,
                                    const float* __restrict__ bl,
                                    const int* __restrict__ qlen,
                                    __half* __restrict__ cmdh)
{
    int b = blockIdx.x, t = blockIdx.y;
    int tid = threadIdx.x, lane = tid & 31, wid = tid >> 5;
    __shared__ float qw[C_];
    __shared__ float att[32];
    const float* qcmd = qcall + (size_t)b * 2048 + t * C_;
    for (int c = tid; c < C_; c += 256) qw[c] = qcmd[c] * Wl[c];
    __syncthreads();
    for (int l = wid; l < L_; l += 8) {
        const float* lr = lstm + ((size_t)b * L_ + l) * C_;
        float s = 0.f;
        for (int c = lane; c < C_; c += 32) s += qw[c] * lr[c];
        for (int o = 16; o; o >>= 1) s += __shfl_xor_sync(0xffffffffu, s, o);
        if (lane == 0) att[l] = s + bl[0];
    }
    __syncthreads();
    if (tid == 0) {
        int Lq = qlen[b];
        float mx = NEGV;
        for (int l = 0; l < Lq; l++) mx = fmaxf(mx, att[l]);
        float sum = 0.f;
        for (int l = 0; l < Lq; l++) { float e = expf(att[l] - mx); att[l] = e; sum += e; }
        float invs = 1.f / sum;
        for (int l = 0; l < Lq; l++) att[l] *= invs;
        for (int l = Lq; l < L_; l++) att[l] = 0.f;
    }
    __syncthreads();
    __half* outr = cmdh + (size_t)(t * B_ + b) * C_;
    for (int c = tid; c < C_; c += 256) {
        float s = 0.f;
#pragma unroll 5
        for (int l = 0; l < L_; l++) s += att[l] * lstm[((size_t)b * L_ + l) * C_ + c];
        outr[c] = __float2half(s);
    }
}

// ---------------- fused entity attention: scores+softmax+P@V ---------------
#define QC 10
#define QS 1536

__device__ __forceinline__ float4 h4f(uint2 v)
{
    __half2* hp = (__half2*)&v;
    float2 f0 = __half22float2(hp[0]);
    float2 f1 = __half22float2(hp[1]);
    float4 o = {f0.x, f0.y, f1.x, f1.y};
    return o;
}

__global__ void ent_attn_kernel(const __half* __restrict__ QKV,
                                const int* __restrict__ entnum,
                                __half* __restrict__ xj_msg)
{
    int b = blockIdx.x, qc = blockIdx.y;
    int tid = threadIdx.x, lane = tid & 31, wid = tid >> 5;
    __shared__ uint32_t Qh[QC * 260];
    __shared__ float Ps[QC * 104];

    for (int i = tid; i < QC * 128; i += 256) {
        int r = i >> 7, c4 = i & 127;
        uint2 v = *(const uint2*)(QKV + ((size_t)(b * N_ + qc * QC + r)) * QS + c4 * 4);
        *(uint2*)&Qh[r * 260 + c4 * 2] = v;
    }
    __syncthreads();
    int en = entnum[b];

    for (int k0 = wid * 2; k0 < N_; k0 += 16) {
        const __half* kr0 = QKV + ((size_t)(b * N_ + k0)) * QS + 512;
        const __half* kr1 = kr0 + QS;
        float a0[QC], a1[QC];
#pragma unroll
        for (int q = 0; q < QC; q++) { a0[q] = 0.f; a1[q] = 0.f; }
#pragma unroll
        for (int t = 0; t < 4; t++) {
            float4 f0 = h4f(*(const uint2*)(kr0 + lane * 4 + t * 128));
            float4 f1 = h4f(*(const uint2*)(kr1 + lane * 4 + t * 128));
#pragma unroll
            for (int q = 0; q < QC; q++) {
                float4 qf = h4f(*(const uint2*)&Qh[q * 260 + lane * 2 + t * 64]);
                a0[q] += qf.x * f0.x + qf.y * f0.y + qf.z * f0.z + qf.w * f0.w;
                a1[q] += qf.x * f1.x + qf.y * f1.y + qf.z * f1.z + qf.w * f1.w;
            }
        }
#pragma unroll
        for (int q = 0; q < QC; q++) {
            for (int o = 16; o; o >>= 1) {
                a0[q] += __shfl_xor_sync(0xffffffffu, a0[q], o);
                a1[q] += __shfl_xor_sync(0xffffffffu, a1[q], o);
            }
        }
        if (lane == 0) {
#pragma unroll
            for (int q = 0; q < QC; q++) {
                Ps[q * 104 + k0]     = (k0 < en)     ? a0[q] * INV_SQRT_C : NEGV;
                Ps[q * 104 + k0 + 1] = (k0 + 1 < en) ? a1[q] * INV_SQRT_C : NEGV;
            }
        }
    }
    __syncthreads();

    for (int r = wid; r < QC; r += 8) {
        float v[4];
#pragma unroll
        for (int t = 0; t < 4; t++) {
            int c = lane + t * 32;
            v[t] = (c < N_) ? Ps[r * 104 + c] : NEGV;
        }
        float mx = fmaxf(fmaxf(v[0], v[1]), fmaxf(v[2], v[3]));
        for (int o = 16; o; o >>= 1) mx = fmaxf(mx, __shfl_xor_sync(0xffffffffu, mx, o));
        float sum = 0.f, e[4];
#pragma unroll
        for (int t = 0; t < 4; t++) { e[t] = expf(v[t] - mx); sum += e[t]; }
        for (int o = 16; o; o >>= 1) sum += __shfl_xor_sync(0xffffffffu, sum, o);
        float invs = 1.f / sum;
#pragma unroll
        for (int t = 0; t < 4; t++) {
            int c = lane + t * 32;
            if (c < N_) Ps[r * 104 + c] = e[t] * invs;
        }
    }
    __syncthreads();

    // P @ V : thread owns column pair (2*tid, 2*tid+1) via __half2
    const __half* Vb = QKV + (size_t)(b * N_) * QS + 1024 + 2 * tid;
    float acc0[QC], acc1[QC];
#pragma unroll
    for (int q = 0; q < QC; q++) { acc0[q] = 0.f; acc1[q] = 0.f; }
#pragma unroll 4
    for (int k = 0; k < N_; k++) {
        float2 v2 = __half22float2(*(const __half2*)(Vb + (size_t)k * QS));
#pragma unroll
        for (int q = 0; q < QC; q++) {
            float p = Ps[q * 104 + k];
            acc0[q] += p * v2.x;
            acc1[q] += p * v2.y;
        }
    }
#pragma unroll
    for (int q = 0; q < QC; q++) {
        size_t row = (size_t)(b * N_ + qc * QC + q);
        *(__half2*)(xj_msg + row * 1536 + 1024 + 2 * tid) = __floats2half2_rn(acc0[q], acc1[q]);
    }
}

// ---------------- host helpers ----------------
static inline void gemm(const __half* A, int lda, const __half* W, int ldw,
                        const float* bias,
                        const float* emul, int mdiv, int eld,
                        float* Cf, __half* Ch, __half* Ch2,
                        const float* Cacc, const __half* CaccH, int ldacc, int accMode,
                        int ldc, int M, int N, int K, int act)
{
    dim3 grid(N / 128, M / 128);
    gemm_h_kernel<<<grid, 256, SM_TOT>>>(A, lda, W, ldw, bias,
                                         emul, mdiv > 0 ? mdiv : 1, eld,
                                         Cf, Ch, Ch2, Cacc, CaccH, ldacc, accMode,
                                         ldc, K, act);
}

extern "C" void kernel_launch(void* const* d_in, const int* in_sizes, int n_in,
                              void* d_out, int out_size)
{
    const float* images     = (const float*)d_in[0];
    const float* q_encoding = (const float*)d_in[1];
    const float* lstm       = (const float*)d_in[2];
    const float* W_initKB   = (const float*)d_in[3];
    const float* b_initKB   = (const float*)d_in[4];
    const float* initMem    = (const float*)d_in[5];
    const float* W_qIn      = (const float*)d_in[6];
    const float* b_qIn      = (const float*)d_in[7];
    const float* W_qIn2     = (const float*)d_in[8];
    const float* b_qIn2     = (const float*)d_in[9];
    const float* W_logit    = (const float*)d_in[10];
    const float* b_logit    = (const float*)d_in[11];
    const float* W_ploc     = (const float*)d_in[12];
    const float* b_ploc     = (const float*)d_in[13];
    const float* W_pctx     = (const float*)d_in[14];
    const float* b_pctx     = (const float*)d_in[15];
    const float* W_q        = (const float*)d_in[16];
    const float* b_q        = (const float*)d_in[17];
    const float* W_k        = (const float*)d_in[18];
    const float* b_k        = (const float*)d_in[19];
    const float* W_v        = (const float*)d_in[20];
    const float* b_v        = (const float*)d_in[21];
    const float* W_pk       = (const float*)d_in[22];
    const float* b_pk       = (const float*)d_in[23];
    const float* W_pv       = (const float*)d_in[24];
    const float* b_pv       = (const float*)d_in[25];
    const float* W_mem      = (const float*)d_in[26];
    const float* b_mem      = (const float*)d_in[27];
    const float* W_comb     = (const float*)d_in[28];
    const float* b_comb     = (const float*)d_in[29];
    const int*   q_length   = (const int*)d_in[30];
    const int*   entity_num = (const int*)d_in[31];

    cudaFuncSetAttribute(gemm_h_kernel, cudaFuncAttributeMaxDynamicSharedMemorySize, SM_TOT);

    float* Sf = 0;  __half* Sh = 0;
    cudaGetSymbolAddress((void**)&Sf, g_scratchf);
    cudaGetSymbolAddress((void**)&Sh, g_scratchh);

    float* P1    = Sf + OFF_P1;
    float* qcall = Sf + OFF_QCALL;
    float* gates = Sf + OFF_GATES;
    float* bqkv  = Sf + OFF_BQKV;
    float* bpkpv = Sf + OFF_BPKPV;
    float* outp  = (float*)d_out;

    __half* imgh  = Sh + HO_IMG;
    __half* xjA   = Sh + HO_XJA;
    __half* xjB   = Sh + HO_XJB;
    __half* QKVbh = Sh + HO_QKVB;
    __half* QKVfh = Sh + HO_QKVF;
    __half* qbh   = Sh + HO_QB;
    __half* cmdh  = Sh + HO_CMD;
    __half* qeh   = Sh + HO_QENC;

    // ---- conversions + bias concats ----
    convw_kernel<<<(CW_TOT + 255) / 256, 256>>>(
        W_initKB, W_qIn, W_qIn2, W_ploc, W_pctx,
        W_q, W_k, W_v, W_pk, W_pv, W_mem, W_comb, Sh + HO_W0);
    norm_img_kernel<<<MR_, 256>>>(images, imgh);
    {
        int n4 = B_ * C_ / 4;
        f2h_kernel<<<(n4 + 255) / 256, 256>>>(q_encoding, qeh, n4);
    }
    cudaMemcpyAsync(bqkv,        b_q,  C_ * 4, cudaMemcpyDeviceToDevice);
    cudaMemcpyAsync(bqkv + C_,   b_k,  C_ * 4, cudaMemcpyDeviceToDevice);
    cudaMemcpyAsync(bqkv + 2*C_, b_v,  C_ * 4, cudaMemcpyDeviceToDevice);
    cudaMemcpyAsync(bpkpv,       b_pk, C_ * 4, cudaMemcpyDeviceToDevice);
    cudaMemcpyAsync(bpkpv + C_,  b_pv, C_ * 4, cudaMemcpyDeviceToDevice);

    // ---- stem + setup ----
    setup_kernel<<<(MR_ * C_ / 8 + 255) / 256, 256>>>(initMem, xjA, gates);
    gemm(imgh, DF_, Sh + HW_INIT, DF_, b_initKB, 0, 1, 0,
         0, xjA, xjB, 0, 0, 0, 0, 1536, MR_, C_, DF_, 0);      // x_loc -> xjA & xjB

    // ---- loop-invariant precomputes ----
    gemm(xjA, 1536, Sh + HW_PLOC, C_, b_ploc, 0, 1, 0,
         P1, 0, 0, 0, 0, 0, 0, C_, MR_, C_, C_, 0);
    gemm(xjA, 1536, Sh + HW_QKV, 1536, bqkv, 0, 1, 0,
         0, QKVbh, 0, 0, 0, 0, 0, 1536, MR_, 1536, C_, 0);

    // ---- command pipeline (all T upfront) ----
    gemm(qeh, C_, Sh + HW_QIN, C_, b_qIn, 0, 1, 0,
         0, qbh, 0, 0, 0, 0, 0, C_, B_, C_, C_, 1);
    gemm(qbh, C_, Sh + HW_QIN2, C_, b_qIn2, 0, 1, 0,
         qcall, 0, 0, 0, 0, 0, 0, 2048, B_, 2048, C_, 0);
    cmd_attn_all_kernel<<<dim3(B_, T_), 256>>>(qcall, lstm, W_logit, b_logit, q_length, cmdh);
    gemm(cmdh, C_, Sh + HW_PKPV, C_, bpkpv, 0, 1, 0,
         gates + 512, 0, 0, 0, 0, 0, 0, 1536, T_ * B_, 1024, C_, 0);

    for (int t = 0; t < T_; t++) {
        __half* cur = (t & 1) ? xjB : xjA;
        __half* nxt = (t & 1) ? xjA : xjB;

        // prod = Linear(x_ctx) * P1 -> cur[:,1024:1536]
        gemm(cur + 512, 1536, Sh + HW_PCTX, C_, b_pctx, P1, 1, C_,
             0, cur + 1024, 0, 0, 0, 0, 0, 1536, MR_, C_, C_, 0);

        // QKV = (partial(x_ctx|prod) + base_h) * gates  -> half
        gemm(cur + 512, 1536, Sh + HW_QKV + 512, 1536, 0,
             gates + (size_t)t * B_ * 1536, N_, 1536,
             0, QKVfh, 0, 0, QKVbh, 1536, 2, 1536, MR_, 1536, 1024, 0);

        // fused entity attention -> msg into cur[:,1024:1536]
        ent_attn_kernel<<<dim3(B_, N_ / QC), 256>>>(QKVfh, entity_num, cur);

        // x_ctx' = Linear([x_ctx, msg]) -> nxt[:,512:1024]
        gemm(cur + 512, 1536, Sh + HW_MEM, 2 * C_, b_mem, 0, 1, 0,
             0, nxt + 512, 0, 0, 0, 0, 0, 1536, MR_, C_, 1024, 0);
    }

    // out = Linear([x_loc, x_ctx])  (xjA holds both contiguously)
    gemm(xjA, 1536, Sh + HW_COMB, 2 * C_, b_comb, 0, 1, 0,
         outp, 0, 0, 0, 0, 0, 0, C_, MR_, C_, 1024, 0);

    (void)in_sizes; (void)n_in; (void)out_size;
}

// round 16
// speedup vs baseline: 1.1596x; 1.0443x over previous
#include <cuda_runtime.h>
#include <cuda_fp16.h>
#include <math.h>
#include <stdint.h>

// ---------------- problem constants ----------------
#define B_   128
#define N_   100
#define L_   30
#define DF_  2112
#define C_   512
#define T_   4
#define MR_  (B_*N_)          // 12800 rows
#define NEGV (-1e30f)
#define INV_SQRT_C 0.044194173824159216f  // 1/sqrt(512)

// ---------------- f32 scratch layout ----------------
#define OFF_P1    ((size_t)0)                         // [12800,512]
#define OFF_QCALL (OFF_P1   + (size_t)MR_*C_)         // [128,2048]
#define OFF_GATES (OFF_QCALL+ (size_t)B_*2048)        // [4*128,1536]
#define OFF_BQKV  (OFF_GATES+ (size_t)T_*B_*1536)     // [1536]
#define OFF_BPKPV (OFF_BQKV + 1536)                   // [1024]
#define SCRF_TOTAL (OFF_BPKPV + 1024)
__device__ __align__(16) float g_scratchf[SCRF_TOTAL];

// ---------------- half scratch layout ----------------
#define HO_IMG    ((size_t)0)                          // [12800,2112] normalized
#define HO_XJA    (HO_IMG  + (size_t)MR_*DF_)          // [12800,1536]
#define HO_XJB    (HO_XJA  + (size_t)MR_*1536)         // [12800,1536]
#define HO_QKVB   (HO_XJB  + (size_t)MR_*1536)         // [12800,1536] base (half)
#define HO_QKVF   (HO_QKVB + (size_t)MR_*1536)         // [12800,1536] gated (half)
#define HO_QB     (HO_QKVF + (size_t)MR_*1536)         // [128,512]
#define HO_CMD    (HO_QB   + (size_t)B_*C_)            // [4*128,512]
#define HO_QENC   (HO_CMD  + (size_t)T_*B_*C_)
#define HO_W0     (HO_QENC + (size_t)B_*C_)
// weight block (contiguous, conversion order)
#define HW_INIT   (HO_W0 + 0)
#define HW_QIN    (HO_W0 + 1081344)
#define HW_QIN2   (HO_W0 + 1343488)
#define HW_PLOC   (HO_W0 + 2392064)
#define HW_PCTX   (HO_W0 + 2654208)
#define HW_QKV    (HO_W0 + 2916352)    // Wq|Wk|Wv rows, [1536,1536]
#define HW_PKPV   (HO_W0 + 5275648)    // Wpk|Wpv rows, [1024,512]
#define HW_MEM    (HO_W0 + 5799936)    // [512,1024]
#define HW_COMB   (HO_W0 + 6324224)    // [512,1024]
#define SCRH_TOTAL (HO_W0 + 6848512)
__device__ __align__(16) __half g_scratchh[SCRH_TOTAL];

// ---------------- generic f32 -> f16 (n % 4 == 0) ----------------
__global__ void f2h_kernel(const float* __restrict__ src, __half* __restrict__ dst, int n4)
{
    int i = blockIdx.x * 256 + threadIdx.x;
    if (i < n4) {
        float4 v = ((const float4*)src)[i];
        __half2 h0 = __floats2half2_rn(v.x, v.y);
        __half2 h1 = __floats2half2_rn(v.z, v.w);
        uint2 o; o.x = *(uint32_t*)&h0; o.y = *(uint32_t*)&h1;
        ((uint2*)dst)[i] = o;
    }
}

// ---------------- merged weight conversion (12 segments) ----------------
#define CW_TOT 1712128
__global__ void convw_kernel(const float* s0, const float* s1, const float* s2,
                             const float* s3, const float* s4, const float* s5,
                             const float* s6, const float* s7, const float* s8,
                             const float* s9, const float* s10, const float* s11,
                             __half* __restrict__ dst)
{
    int i = blockIdx.x * 256 + threadIdx.x;
    if (i >= CW_TOT) return;
    const float* src; int off;
    if      (i < 270336)  { src = s0;  off = i; }
    else if (i < 335872)  { src = s1;  off = i - 270336; }
    else if (i < 598016)  { src = s2;  off = i - 335872; }
    else if (i < 663552)  { src = s3;  off = i - 598016; }
    else if (i < 729088)  { src = s4;  off = i - 663552; }
    else if (i < 925696)  { src = s5;  off = i - 729088; }
    else if (i < 1122304) { src = s6;  off = i - 925696; }
    else if (i < 1318912) { src = s7;  off = i - 1122304; }
    else if (i < 1384448) { src = s8;  off = i - 1318912; }
    else if (i < 1449984) { src = s9;  off = i - 1384448; }
    else if (i < 1581056) { src = s10; off = i - 1449984; }
    else                  { src = s11; off = i - 1581056; }
    float4 v = ((const float4*)src)[off];
    __half2 h0 = __floats2half2_rn(v.x, v.y);
    __half2 h1 = __floats2half2_rn(v.z, v.w);
    uint2 o; o.x = *(uint32_t*)&h0; o.y = *(uint32_t*)&h1;
    ((uint2*)dst)[i] = o;
}

// ---------------- fused row-normalize + f32->f16 of images ------------------
__global__ void norm_img_kernel(const float* __restrict__ img, __half* __restrict__ dst)
{
    int row = blockIdx.x;
    int tid = threadIdx.x;
    const float4* r = (const float4*)(img + (size_t)row * DF_);  // 528 float4
    float4 v[3];
    float s = 0.f;
#pragma unroll
    for (int j = 0; j < 3; j++) {
        int idx = tid + j * 256;
        if (idx < 528) {
            v[j] = r[idx];
            s += v[j].x * v[j].x + v[j].y * v[j].y + v[j].z * v[j].z + v[j].w * v[j].w;
        }
    }
    __shared__ float red[256];
    red[tid] = s; __syncthreads();
    for (int o = 128; o > 0; o >>= 1) { if (tid < o) red[tid] += red[tid + o]; __syncthreads(); }
    float inv = 1.f / fmaxf(sqrtf(red[0]), 1e-12f);
    uint2* out = (uint2*)(dst + (size_t)row * DF_);
#pragma unroll
    for (int j = 0; j < 3; j++) {
        int idx = tid + j * 256;
        if (idx < 528) {
            __half2 h0 = __floats2half2_rn(v[j].x * inv, v[j].y * inv);
            __half2 h1 = __floats2half2_rn(v[j].z * inv, v[j].w * inv);
            uint2 o; o.x = *(uint32_t*)&h0; o.y = *(uint32_t*)&h1;
            out[idx] = o;
        }
    }
}

// ---------------- setup: init x_ctx slice of xjA + ones gates (vectorized) --
__global__ void setup_kernel(const float* __restrict__ initMem,
                             __half* __restrict__ xjA, float* __restrict__ gates)
{
    int i = blockIdx.x * 256 + threadIdx.x;
    if (i < MR_ * C_ / 8) {
        int m = i >> 6, c8 = (i & 63) * 8;
        float4 a = *(const float4*)(initMem + c8);
        float4 b = *(const float4*)(initMem + c8 + 4);
        __half2 h0 = __floats2half2_rn(a.x, a.y);
        __half2 h1 = __floats2half2_rn(a.z, a.w);
        __half2 h2 = __floats2half2_rn(b.x, b.y);
        __half2 h3 = __floats2half2_rn(b.z, b.w);
        uint4 o;
        o.x = *(uint32_t*)&h0; o.y = *(uint32_t*)&h1;
        o.z = *(uint32_t*)&h2; o.w = *(uint32_t*)&h3;
        *(uint4*)(xjA + (size_t)m * 1536 + 512 + c8) = o;
    }
    if (i < T_ * B_ * C_ / 4) {
        int r = i >> 7, c4 = (i & 127) * 4;
        float4 one = {1.f, 1.f, 1.f, 1.f};
        *(float4*)(gates + (size_t)r * 1536 + c4) = one;
    }
}

// ============================================================================
// FP16 tensor-core NT GEMM: C[m,n] = epi( sum_k A[m,k]*W[n,k] ), f32 accum.
// 128x128 tile, BK=64, 3-stage cp.async, ldmatrix, one sync per k64 iter.
// ============================================================================
#define STAGE_B 18432              // 128 rows * 144 B
#define SMB (3*STAGE_B)
#define SM_TOT (6*STAGE_B)         // 110592

__device__ __forceinline__ void cp16(uint32_t dst, const void* src)
{
    asm volatile("cp.async.cg.shared.global [%0], [%1], 16;"
                 :: "r"(dst), "l"(__cvta_generic_to_global(src)) : "memory");
}

__device__ __forceinline__ void ldsm4(uint32_t& r0, uint32_t& r1, uint32_t& r2, uint32_t& r3,
                                      uint32_t addr)
{
    asm volatile("ldmatrix.sync.aligned.m8n8.x4.shared.b16 {%0,%1,%2,%3}, [%4];"
                 : "=r"(r0), "=r"(r1), "=r"(r2), "=r"(r3) : "r"(addr));
}

__global__ void __launch_bounds__(256, 2) gemm_h_kernel(
    const __half* __restrict__ A, int lda,
    const __half* __restrict__ W, int ldw,
    const float* __restrict__ bias,
    const float* __restrict__ emul, int emul_mdiv, int emul_ld,
    float* __restrict__ Cf, __half* __restrict__ Ch, __half* __restrict__ Ch2,
    const float* __restrict__ Cacc, const __half* __restrict__ CaccH,
    int ldacc, int accMode,
    int ldc, int K, int act)
{
    extern __shared__ __align__(16) char smem[];
    uint32_t sb;
    asm("{ .reg .u64 t; cvta.to.shared.u64 t, %1; cvt.u32.u64 %0, t; }" : "=r"(sb) : "l"(smem));

    const int tid  = threadIdx.x;
    const int lane = tid & 31;
    const int wid  = tid >> 5;
    const int g    = lane >> 2;
    const int tg   = lane & 3;
    const int wm   = (wid >> 2) * 64;
    const int wn   = (wid & 3) * 32;
    const int mBase = blockIdx.y * 128, nBase = blockIdx.x * 128;

    const __half* gA[4]; const __half* gW[4];
    uint32_t sA[4], sB[4];
#pragma unroll
    for (int j = 0; j < 4; j++) {
        int idx = tid + j * 256;
        int row = idx >> 3, kc = idx & 7;
        gA[j] = A + (size_t)(mBase + row) * lda + kc * 8;
        gW[j] = W + (size_t)(nBase + row) * ldw + kc * 8;
        sA[j] = sb + row * 144 + kc * 16;
        sB[j] = sb + SMB + row * 144 + kc * 16;
    }

    uint32_t aoff[4], boff[2];
    {
        int r16 = lane & 15, kh = lane >> 4;
#pragma unroll
        for (int ma = 0; ma < 4; ma++)
            aoff[ma] = sb + (wm + ma * 16 + r16) * 144 + kh * 16;
        int br = ((lane >> 3) & 1) * 8 + (lane & 7);
#pragma unroll
        for (int nb = 0; nb < 2; nb++)
            boff[nb] = sb + SMB + (wn + nb * 16 + br) * 144 + kh * 16;
    }

    float acc[4][4][4];
#pragma unroll
    for (int i = 0; i < 4; i++)
#pragma unroll
        for (int j = 0; j < 4; j++)
#pragma unroll
            for (int r = 0; r < 4; r++) acc[i][j][r] = 0.f;

    const int nk = K >> 6;
#pragma unroll
    for (int s = 0; s < 2; s++) {
        if (s < nk) {
            int ko = s << 6;
#pragma unroll
            for (int j = 0; j < 4; j++) {
                cp16(sA[j] + s * STAGE_B, gA[j] + ko);
                cp16(sB[j] + s * STAGE_B, gW[j] + ko);
            }
        }
        asm volatile("cp.async.commit_group;" ::: "memory");
    }

    for (int k = 0; k < nk; ++k) {
        asm volatile("cp.async.wait_group 1;" ::: "memory");
        __syncthreads();
        if (k + 2 < nk) {
            int s = (k + 2) % 3;
            int ko = (k + 2) << 6;
#pragma unroll
            for (int j = 0; j < 4; j++) {
                cp16(sA[j] + s * STAGE_B, gA[j] + ko);
                cp16(sB[j] + s * STAGE_B, gW[j] + ko);
            }
        }
        asm volatile("cp.async.commit_group;" ::: "memory");

        const uint32_t st = (k % 3) * STAGE_B;
#pragma unroll
        for (int sub = 0; sub < 4; sub++) {
            const uint32_t kb = st + sub * 32;
            uint32_t af[4][4], bf[4][2];
#pragma unroll
            for (int ma = 0; ma < 4; ma++)
                ldsm4(af[ma][0], af[ma][1], af[ma][2], af[ma][3], aoff[ma] + kb);
#pragma unroll
            for (int nb = 0; nb < 2; nb++) {
                uint32_t b0, b1, b2, b3;
                ldsm4(b0, b1, b2, b3, boff[nb] + kb);
                bf[2 * nb][0] = b0; bf[2 * nb + 1][0] = b1;
                bf[2 * nb][1] = b2; bf[2 * nb + 1][1] = b3;
            }
#pragma unroll
            for (int ma = 0; ma < 4; ma++)
#pragma unroll
                for (int na = 0; na < 4; na++) {
                    asm volatile(
                        "mma.sync.aligned.m16n8k16.row.col.f32.f16.f16.f32 "
                        "{%0,%1,%2,%3}, {%4,%5,%6,%7}, {%8,%9}, {%0,%1,%2,%3};"
                        : "+f"(acc[ma][na][0]), "+f"(acc[ma][na][1]),
                          "+f"(acc[ma][na][2]), "+f"(acc[ma][na][3])
                        : "r"(af[ma][0]), "r"(af[ma][1]), "r"(af[ma][2]), "r"(af[ma][3]),
                          "r"(bf[na][0]), "r"(bf[na][1]));
                }
        }
    }

    // -------- epilogue --------
#pragma unroll
    for (int ma = 0; ma < 4; ma++) {
#pragma unroll
        for (int half = 0; half < 2; half++) {
            int mr = mBase + wm + ma * 16 + g + half * 8;
            const float* em = emul ? (emul + (size_t)(mr / emul_mdiv) * emul_ld) : (const float*)0;
#pragma unroll
            for (int na = 0; na < 4; na++) {
                int nc = nBase + wn + na * 8 + 2 * tg;
                float v0 = acc[ma][na][half * 2 + 0];
                float v1 = acc[ma][na][half * 2 + 1];
                if (bias) { v0 += bias[nc]; v1 += bias[nc + 1]; }
                if (accMode == 2) {
                    if (CaccH) {
                        __half2 o = *(const __half2*)(CaccH + (size_t)mr * ldacc + nc);
                        float2 f = __half22float2(o);
                        v0 += f.x; v1 += f.y;
                    } else {
                        float2 o = *(const float2*)(Cacc + (size_t)mr * ldacc + nc);
                        v0 += o.x; v1 += o.y;
                    }
                }
                if (em)   { v0 *= em[nc];   v1 *= em[nc + 1]; }
                if (act)  {
                    v0 = (v0 > 0.f) ? v0 : expm1f(v0);
                    v1 = (v1 > 0.f) ? v1 : expm1f(v1);
                }
                if (accMode == 1) {
                    float2 o = *(const float2*)(Cacc + (size_t)mr * ldacc + nc);
                    v0 += o.x; v1 += o.y;
                }
                if (Cf) {
                    float2 ov = {v0, v1};
                    *(float2*)(Cf + (size_t)mr * ldc + nc) = ov;
                }
                if (Ch) {
                    __half2 hv = __floats2half2_rn(v0, v1);
                    *(__half2*)(Ch + (size_t)mr * ldc + nc) = hv;
                    if (Ch2) *(__half2*)(Ch2 + (size_t)mr * ldc + nc) = hv;
                }
            }
        }
    }
}

// ---------------- command attention (all T at once) -------------------------
__global__ void cmd_attn_all_kernel(const float* __restrict__ qcall,
                                    const float* __restrict__ lstm,
                                    const float* __restrict__ Wl,
                                    const float* __restrict__ bl,
                                    const int* __restrict__ qlen,
                                    __half* __restrict__ cmdh)
{
    int b = blockIdx.x, t = blockIdx.y;
    int tid = threadIdx.x, lane = tid & 31, wid = tid >> 5;
    __shared__ float qw[C_];
    __shared__ float att[32];
    const float* qcmd = qcall + (size_t)b * 2048 + t * C_;
    for (int c = tid; c < C_; c += 256) qw[c] = qcmd[c] * Wl[c];
    __syncthreads();
    for (int l = wid; l < L_; l += 8) {
        const float* lr = lstm + ((size_t)b * L_ + l) * C_;
        float s = 0.f;
        for (int c = lane; c < C_; c += 32) s += qw[c] * lr[c];
        for (int o = 16; o; o >>= 1) s += __shfl_xor_sync(0xffffffffu, s, o);
        if (lane == 0) att[l] = s + bl[0];
    }
    __syncthreads();
    if (tid == 0) {
        int Lq = qlen[b];
        float mx = NEGV;
        for (int l = 0; l < Lq; l++) mx = fmaxf(mx, att[l]);
        float sum = 0.f;
        for (int l = 0; l < Lq; l++) { float e = expf(att[l] - mx); att[l] = e; sum += e; }
        float invs = 1.f / sum;
        for (int l = 0; l < Lq; l++) att[l] *= invs;
        for (int l = Lq; l < L_; l++) att[l] = 0.f;
    }
    __syncthreads();
    __half* outr = cmdh + (size_t)(t * B_ + b) * C_;
    for (int c = tid; c < C_; c += 256) {
        float s = 0.f;
#pragma unroll 5
        for (int l = 0; l < L_; l++) s += att[l] * lstm[((size_t)b * L_ + l) * C_ + c];
        outr[c] = __float2half(s);
    }
}

// ---------------- fused entity attention: scores+softmax+P@V ---------------
#define QC 10
#define QS 1536

__device__ __forceinline__ float4 h4f(uint2 v)
{
    __half2* hp = (__half2*)&v;
    float2 f0 = __half22float2(hp[0]);
    float2 f1 = __half22float2(hp[1]);
    float4 o = {f0.x, f0.y, f1.x, f1.y};
    return o;
}

__global__ void ent_attn_kernel(const __half* __restrict__ QKV,
                                const int* __restrict__ entnum,
                                __half* __restrict__ xj_msg)
{
    int b = blockIdx.x, qc = blockIdx.y;
    int tid = threadIdx.x, lane = tid & 31, wid = tid >> 5;
    __shared__ uint32_t Qh[QC * 260];
    __shared__ float Ps[QC * 104];

    for (int i = tid; i < QC * 128; i += 256) {
        int r = i >> 7, c4 = i & 127;
        uint2 v = *(const uint2*)(QKV + ((size_t)(b * N_ + qc * QC + r)) * QS + c4 * 4);
        *(uint2*)&Qh[r * 260 + c4 * 2] = v;
    }
    __syncthreads();
    int en = entnum[b];

    for (int k0 = wid * 2; k0 < N_; k0 += 16) {
        const __half* kr0 = QKV + ((size_t)(b * N_ + k0)) * QS + 512;
        const __half* kr1 = kr0 + QS;
        float a0[QC], a1[QC];
#pragma unroll
        for (int q = 0; q < QC; q++) { a0[q] = 0.f; a1[q] = 0.f; }
#pragma unroll
        for (int t = 0; t < 4; t++) {
            float4 f0 = h4f(*(const uint2*)(kr0 + lane * 4 + t * 128));
            float4 f1 = h4f(*(const uint2*)(kr1 + lane * 4 + t * 128));
#pragma unroll
            for (int q = 0; q < QC; q++) {
                float4 qf = h4f(*(const uint2*)&Qh[q * 260 + lane * 2 + t * 64]);
                a0[q] += qf.x * f0.x + qf.y * f0.y + qf.z * f0.z + qf.w * f0.w;
                a1[q] += qf.x * f1.x + qf.y * f1.y + qf.z * f1.z + qf.w * f1.w;
            }
        }
#pragma unroll
        for (int q = 0; q < QC; q++) {
            for (int o = 16; o; o >>= 1) {
                a0[q] += __shfl_xor_sync(0xffffffffu, a0[q], o);
                a1[q] += __shfl_xor_sync(0xffffffffu, a1[q], o);
            }
        }
        if (lane == 0) {
#pragma unroll
            for (int q = 0; q < QC; q++) {
                Ps[q * 104 + k0]     = (k0 < en)     ? a0[q] * INV_SQRT_C : NEGV;
                Ps[q * 104 + k0 + 1] = (k0 + 1 < en) ? a1[q] * INV_SQRT_C : NEGV;
            }
        }
    }
    __syncthreads();

    for (int r = wid; r < QC; r += 8) {
        float v[4];
#pragma unroll
        for (int t = 0; t < 4; t++) {
            int c = lane + t * 32;
            v[t] = (c < N_) ? Ps[r * 104 + c] : NEGV;
        }
        float mx = fmaxf(fmaxf(v[0], v[1]), fmaxf(v[2], v[3]));
        for (int o = 16; o; o >>= 1) mx = fmaxf(mx, __shfl_xor_sync(0xffffffffu, mx, o));
        float sum = 0.f, e[4];
#pragma unroll
        for (int t = 0; t < 4; t++) { e[t] = expf(v[t] - mx); sum += e[t]; }
        for (int o = 16; o; o >>= 1) sum += __shfl_xor_sync(0xffffffffu, sum, o);
        float invs = 1.f / sum;
#pragma unroll
        for (int t = 0; t < 4; t++) {
            int c = lane + t * 32;
            if (c < N_) Ps[r * 104 + c] = e[t] * invs;
        }
    }
    __syncthreads();

    // P @ V : thread owns column pair (2*tid, 2*tid+1) via __half2
    const __half* Vb = QKV + (size_t)(b * N_) * QS + 1024 + 2 * tid;
    float acc0[QC], acc1[QC];
#pragma unroll
    for (int q = 0; q < QC; q++) { acc0[q] = 0.f; acc1[q] = 0.f; }
#pragma unroll 4
    for (int k = 0; k < N_; k++) {
        float2 v2 = __half22float2(*(const __half2*)(Vb + (size_t)k * QS));
#pragma unroll
        for (int q = 0; q < QC; q++) {
            float p = Ps[q * 104 + k];
            acc0[q] += p * v2.x;
            acc1[q] += p * v2.y;
        }
    }
#pragma unroll
    for (int q = 0; q < QC; q++) {
        size_t row = (size_t)(b * N_ + qc * QC + q);
        *(__half2*)(xj_msg + row * 1536 + 1024 + 2 * tid) = __floats2half2_rn(acc0[q], acc1[q]);
    }
}

// ---------------- host helpers ----------------
static inline void gemm_s(cudaStream_t st,
                          const __half* A, int lda, const __half* W, int ldw,
                          const float* bias,
                          const float* emul, int mdiv, int eld,
                          float* Cf, __half* Ch, __half* Ch2,
                          const float* Cacc, const __half* CaccH, int ldacc, int accMode,
                          int ldc, int M, int N, int K, int act)
{
    dim3 grid(N / 128, M / 128);
    gemm_h_kernel<<<grid, 256, SM_TOT, st>>>(A, lda, W, ldw, bias,
                                             emul, mdiv > 0 ? mdiv : 1, eld,
                                             Cf, Ch, Ch2, Cacc, CaccH, ldacc, accMode,
                                             ldc, K, act);
}

extern "C" void kernel_launch(void* const* d_in, const int* in_sizes, int n_in,
                              void* d_out, int out_size)
{
    const float* images     = (const float*)d_in[0];
    const float* q_encoding = (const float*)d_in[1];
    const float* lstm       = (const float*)d_in[2];
    const float* W_initKB   = (const float*)d_in[3];
    const float* b_initKB   = (const float*)d_in[4];
    const float* initMem    = (const float*)d_in[5];
    const float* W_qIn      = (const float*)d_in[6];
    const float* b_qIn      = (const float*)d_in[7];
    const float* W_qIn2     = (const float*)d_in[8];
    const float* b_qIn2     = (const float*)d_in[9];
    const float* W_logit    = (const float*)d_in[10];
    const float* b_logit    = (const float*)d_in[11];
    const float* W_ploc     = (const float*)d_in[12];
    const float* b_ploc     = (const float*)d_in[13];
    const float* W_pctx     = (const float*)d_in[14];
    const float* b_pctx     = (const float*)d_in[15];
    const float* W_q        = (const float*)d_in[16];
    const float* b_q        = (const float*)d_in[17];
    const float* W_k        = (const float*)d_in[18];
    const float* b_k        = (const float*)d_in[19];
    const float* W_v        = (const float*)d_in[20];
    const float* b_v        = (const float*)d_in[21];
    const float* W_pk       = (const float*)d_in[22];
    const float* b_pk       = (const float*)d_in[23];
    const float* W_pv       = (const float*)d_in[24];
    const float* b_pv       = (const float*)d_in[25];
    const float* W_mem      = (const float*)d_in[26];
    const float* b_mem      = (const float*)d_in[27];
    const float* W_comb     = (const float*)d_in[28];
    const float* b_comb     = (const float*)d_in[29];
    const int*   q_length   = (const int*)d_in[30];
    const int*   entity_num = (const int*)d_in[31];

    cudaFuncSetAttribute(gemm_h_kernel, cudaFuncAttributeMaxDynamicSharedMemorySize, SM_TOT);

    // side stream + fork/join events (created once on the first, uncaptured call)
    static cudaStream_t s1 = 0;
    static cudaEvent_t ev0 = 0, evS = 0, ev1 = 0, ev2 = 0;
    if (!s1) {
        cudaStreamCreateWithFlags(&s1, cudaStreamNonBlocking);
        cudaEventCreateWithFlags(&ev0, cudaEventDisableTiming);
        cudaEventCreateWithFlags(&evS, cudaEventDisableTiming);
        cudaEventCreateWithFlags(&ev1, cudaEventDisableTiming);
        cudaEventCreateWithFlags(&ev2, cudaEventDisableTiming);
    }
    cudaStream_t s0 = 0;

    float* Sf = 0;  __half* Sh = 0;
    cudaGetSymbolAddress((void**)&Sf, g_scratchf);
    cudaGetSymbolAddress((void**)&Sh, g_scratchh);

    float* P1    = Sf + OFF_P1;
    float* qcall = Sf + OFF_QCALL;
    float* gates = Sf + OFF_GATES;
    float* bqkv  = Sf + OFF_BQKV;
    float* bpkpv = Sf + OFF_BPKPV;
    float* outp  = (float*)d_out;

    __half* imgh  = Sh + HO_IMG;
    __half* xjA   = Sh + HO_XJA;
    __half* xjB   = Sh + HO_XJB;
    __half* QKVbh = Sh + HO_QKVB;
    __half* QKVfh = Sh + HO_QKVF;
    __half* qbh   = Sh + HO_QB;
    __half* cmdh  = Sh + HO_CMD;
    __half* qeh   = Sh + HO_QENC;

    // ---- conversions + bias concats (stream 0) ----
    convw_kernel<<<(CW_TOT + 255) / 256, 256, 0, s0>>>(
        W_initKB, W_qIn, W_qIn2, W_ploc, W_pctx,
        W_q, W_k, W_v, W_pk, W_pv, W_mem, W_comb, Sh + HO_W0);
    norm_img_kernel<<<MR_, 256, 0, s0>>>(images, imgh);
    {
        int n4 = B_ * C_ / 4;
        f2h_kernel<<<(n4 + 255) / 256, 256, 0, s0>>>(q_encoding, qeh, n4);
    }
    cudaMemcpyAsync(bqkv,        b_q,  C_ * 4, cudaMemcpyDeviceToDevice, s0);
    cudaMemcpyAsync(bqkv + C_,   b_k,  C_ * 4, cudaMemcpyDeviceToDevice, s0);
    cudaMemcpyAsync(bqkv + 2*C_, b_v,  C_ * 4, cudaMemcpyDeviceToDevice, s0);
    cudaMemcpyAsync(bpkpv,       b_pk, C_ * 4, cudaMemcpyDeviceToDevice, s0);
    cudaMemcpyAsync(bpkpv + C_,  b_pv, C_ * 4, cudaMemcpyDeviceToDevice, s0);
    cudaEventRecord(ev0, s0);

    // ---- side stream: command pipeline (all T upfront) ----
    cudaStreamWaitEvent(s1, ev0, 0);
    gemm_s(s1, qeh, C_, Sh + HW_QIN, C_, b_qIn, 0, 1, 0,
           0, qbh, 0, 0, 0, 0, 0, C_, B_, C_, C_, 1);
    gemm_s(s1, qbh, C_, Sh + HW_QIN2, C_, b_qIn2, 0, 1, 0,
           qcall, 0, 0, 0, 0, 0, 0, 2048, B_, 2048, C_, 0);
    cmd_attn_all_kernel<<<dim3(B_, T_), 256, 0, s1>>>(qcall, lstm, W_logit, b_logit,
                                                      q_length, cmdh);
    gemm_s(s1, cmdh, C_, Sh + HW_PKPV, C_, bpkpv, 0, 1, 0,
           gates + 512, 0, 0, 0, 0, 0, 0, 1536, T_ * B_, 1024, C_, 0);
    cudaEventRecord(ev1, s1);

    // ---- main stream: stem + setup ----
    setup_kernel<<<(MR_ * C_ / 8 + 255) / 256, 256, 0, s0>>>(initMem, xjA, gates);
    gemm_s(s0, imgh, DF_, Sh + HW_INIT, DF_, b_initKB, 0, 1, 0,
           0, xjA, xjB, 0, 0, 0, 0, 1536, MR_, C_, DF_, 0);    // x_loc -> xjA & xjB
    cudaEventRecord(evS, s0);

    // ---- side stream: P1 (overlaps QKV-base on s0) ----
    cudaStreamWaitEvent(s1, evS, 0);
    gemm_s(s1, xjA, 1536, Sh + HW_PLOC, C_, b_ploc, 0, 1, 0,
           P1, 0, 0, 0, 0, 0, 0, C_, MR_, C_, C_, 0);
    cudaEventRecord(ev2, s1);

    // ---- main stream: QKV base ----
    gemm_s(s0, xjA, 1536, Sh + HW_QKV, 1536, bqkv, 0, 1, 0,
           0, QKVbh, 0, 0, 0, 0, 0, 1536, MR_, 1536, C_, 0);

    // join side stream before the iteration loop
    cudaStreamWaitEvent(s0, ev1, 0);
    cudaStreamWaitEvent(s0, ev2, 0);

    for (int t = 0; t < T_; t++) {
        __half* cur = (t & 1) ? xjB : xjA;
        __half* nxt = (t & 1) ? xjA : xjB;

        // prod = Linear(x_ctx) * P1 -> cur[:,1024:1536]
        gemm_s(s0, cur + 512, 1536, Sh + HW_PCTX, C_, b_pctx, P1, 1, C_,
               0, cur + 1024, 0, 0, 0, 0, 0, 1536, MR_, C_, C_, 0);

        // QKV = (partial(x_ctx|prod) + base_h) * gates  -> half
        gemm_s(s0, cur + 512, 1536, Sh + HW_QKV + 512, 1536, 0,
               gates + (size_t)t * B_ * 1536, N_, 1536,
               0, QKVfh, 0, 0, QKVbh, 1536, 2, 1536, MR_, 1536, 1024, 0);

        // fused entity attention -> msg into cur[:,1024:1536]
        ent_attn_kernel<<<dim3(B_, N_ / QC), 256, 0, s0>>>(QKVfh, entity_num, cur);

        // x_ctx' = Linear([x_ctx, msg]) -> nxt[:,512:1024]
        gemm_s(s0, cur + 512, 1536, Sh + HW_MEM, 2 * C_, b_mem, 0, 1, 0,
               0, nxt + 512, 0, 0, 0, 0, 0, 1536, MR_, C_, 1024, 0);
    }

    // out = Linear([x_loc, x_ctx])  (xjA holds both contiguously)
    gemm_s(s0, xjA, 1536, Sh + HW_COMB, 2 * C_, b_comb, 0, 1, 0,
           outp, 0, 0, 0, 0, 0, 0, C_, MR_, C_, 1024, 0);

    (void)in_sizes; (void)n_in; (void)out_size;
}